// round 14
// baseline (speedup 1.0000x reference)
#include <cuda_runtime.h>
#include <cuda_bf16.h>
#include <cstdint>

// Histogram_15126874816754:
//   out[b, (p>0), y, x] += |p|/STD  over N events, then clip at 1.0.
// Settled facts:
//   R7/R8: value-returning atomics ~60% slower than red -> use red.
//   R9:    scatter at the ~2 cyc/lane divergent-RED floor (~55-57us).
//   R11:   DMA memset loses L2 residency -> SM-visible fill required.
//   R12:   PDL can't overlap (no valid early trigger).
//   R13:   STG fill capped ~3000 B/cyc regardless of cache policy.
// R14 experiment: TMA bulk-store zero fill (UBLKCP smem->gmem), targeting
// the ~6300 B/cyc bulk write path. Scatter/clip identical to the 73.7 best.

#define INV_STD_C  (1.0f / 20.0f)
#define CLIP_MAX_C 1.0f
#define ZCHUNK     16384   // 16 KB bulk-store chunk

__device__ __forceinline__ uint64_t make_evict_last_policy() {
    uint64_t pol;
    asm("createpolicy.fractional.L2::evict_last.b64 %0, 1.0;" : "=l"(pol));
    return pol;
}

// fire-and-forget RED with L2 evict_last hint (keeps image resident)
__device__ __forceinline__ void red_add_f32_evict_last(float* p, float v, uint64_t pol) {
    asm volatile(
        "red.relaxed.gpu.global.L2::cache_hint.add.f32 [%0], %1, %2;"
        :: "l"(p), "f"(v), "l"(pol) : "memory");
}

// ---------------------------------------------------------------------------
// Zero pass via TMA bulk stores: each block zeroes a 16 KB smem buffer once,
// then bulk-copies it to its assigned image chunks. Bulk writes land as
// dirty L2 lines (write-back coherence point), preserving residency.
// ---------------------------------------------------------------------------
__global__ void __launch_bounds__(256)
hist_zero_tma_kernel(float* __restrict__ out, long long nbytes)
{
    __shared__ __align__(128) char zbuf[ZCHUNK];

    // zero the smem staging buffer (once per block)
    for (int i = threadIdx.x * 16; i < ZCHUNK; i += blockDim.x * 16)
        *reinterpret_cast<float4*>(zbuf + i) = make_float4(0.f, 0.f, 0.f, 0.f);
    __syncthreads();
    asm volatile("fence.proxy.async;" ::: "memory");

    const long long nchunks = nbytes / ZCHUNK;

    if (threadIdx.x == 0) {
        uint32_t smem_addr = (uint32_t)__cvta_generic_to_shared(zbuf);
        for (long long c = blockIdx.x; c < nchunks; c += gridDim.x) {
            char* dst = reinterpret_cast<char*>(out) + c * (long long)ZCHUNK;
            asm volatile(
                "cp.async.bulk.global.shared::cta.bulk_group [%0], [%1], %2;"
                :: "l"(dst), "r"(smem_addr), "n"(ZCHUNK) : "memory");
        }
        asm volatile("cp.async.bulk.commit_group;" ::: "memory");
        asm volatile("cp.async.bulk.wait_group 0;" ::: "memory");
    }

    // scalar tail (nbytes % ZCHUNK; float-granular since nbytes = 4*out_size)
    if (blockIdx.x == 0) {
        const long long tail_f = (nchunks * ZCHUNK) / 4;
        const long long n_f    = nbytes / 4;
        for (long long k = tail_f + threadIdx.x; k < n_f; k += blockDim.x)
            out[k] = 0.0f;
    }
}

// ---------------------------------------------------------------------------
// Scatter: 8 events/thread, front-batched __ldcs input loads (evict-first),
// RED.E.ADD.F32 with evict_last. At the divergent-atomic lane floor.
// ---------------------------------------------------------------------------
__global__ void __launch_bounds__(256)
hist_scatter_kernel(const int4* __restrict__ xs,
                    const int4* __restrict__ ys,
                    const float4* __restrict__ ps,
                    const int4* __restrict__ bs,
                    const int* __restrict__ wp,
                    const int* __restrict__ hp,
                    float* __restrict__ out,
                    int n8)
{
    const int W = __ldg(wp);
    const int H = __ldg(hp);
    const uint64_t pol = make_evict_last_policy();

    const int i = blockIdx.x * blockDim.x + threadIdx.x;
    if (i >= n8) return;

    const int4   x0 = __ldcs(xs + 2 * i),  x1 = __ldcs(xs + 2 * i + 1);
    const int4   y0 = __ldcs(ys + 2 * i),  y1 = __ldcs(ys + 2 * i + 1);
    const float4 p0 = __ldcs(ps + 2 * i),  p1 = __ldcs(ps + 2 * i + 1);
    const int4   b0 = __ldcs(bs + 2 * i),  b1 = __ldcs(bs + 2 * i + 1);

#define SCATTER_ONE(xx, yy, pp, bb)                                        \
    {                                                                      \
        const int pos = (pp) > 0.0f;                                       \
        const int idx = (((bb) * 2 + pos) * H + (yy)) * W + (xx);          \
        red_add_f32_evict_last(out + idx, fabsf(pp) * INV_STD_C, pol);     \
    }

    SCATTER_ONE(x0.x, y0.x, p0.x, b0.x)
    SCATTER_ONE(x0.y, y0.y, p0.y, b0.y)
    SCATTER_ONE(x0.z, y0.z, p0.z, b0.z)
    SCATTER_ONE(x0.w, y0.w, p0.w, b0.w)
    SCATTER_ONE(x1.x, y1.x, p1.x, b1.x)
    SCATTER_ONE(x1.y, y1.y, p1.y, b1.y)
    SCATTER_ONE(x1.z, y1.z, p1.z, b1.z)
    SCATTER_ONE(x1.w, y1.w, p1.w, b1.w)
#undef SCATTER_ONE
}

__global__ void
hist_scatter_tail_kernel(const int* __restrict__ xs,
                         const int* __restrict__ ys,
                         const float* __restrict__ ps,
                         const int* __restrict__ bs,
                         const int* __restrict__ wp,
                         const int* __restrict__ hp,
                         float* __restrict__ out,
                         int start, int n)
{
    const int k = start + blockIdx.x * blockDim.x + threadIdx.x;
    if (k >= n) return;
    const int W = __ldg(wp);
    const int H = __ldg(hp);
    const float pk = ps[k];
    const int pos = pk > 0.0f;
    const int idx = ((bs[k] * 2 + pos) * H + ys[k]) * W + xs[k];
    atomicAdd(out + idx, fabsf(pk) * INV_STD_C);
}

// ---------------------------------------------------------------------------
// Clip: one float4/thread, __ldcg reads (image L2-resident), store only if a
// component exceeds 1.0 (rare) -> write stream ~vanishes.
// ---------------------------------------------------------------------------
__global__ void __launch_bounds__(256)
hist_clip_kernel(float* __restrict__ out, int n)
{
    const int n4 = n >> 2;
    const int i = blockIdx.x * blockDim.x + threadIdx.x;

    if (i < n4) {
        float4* o4 = reinterpret_cast<float4*>(out);
        float4 v = __ldcg(o4 + i);
        if (v.x > CLIP_MAX_C || v.y > CLIP_MAX_C ||
            v.z > CLIP_MAX_C || v.w > CLIP_MAX_C) {
            v.x = fminf(v.x, CLIP_MAX_C);
            v.y = fminf(v.y, CLIP_MAX_C);
            v.z = fminf(v.z, CLIP_MAX_C);
            v.w = fminf(v.w, CLIP_MAX_C);
            o4[i] = v;
        }
    } else if (i == n4) {
        for (int k = n4 * 4; k < n; ++k) {
            const float v = out[k];
            if (v > CLIP_MAX_C) out[k] = CLIP_MAX_C;
        }
    }
}

// ---------------------------------------------------------------------------
extern "C" void kernel_launch(void* const* d_in, const int* in_sizes, int n_in,
                              void* d_out, int out_size)
{
    const int*   xs = (const int*)  d_in[0];
    const int*   ys = (const int*)  d_in[1];
    const float* ps = (const float*)d_in[2];
    const int*   bs = (const int*)  d_in[3];
    const int*   wp = (const int*)  d_in[4];
    const int*   hp = (const int*)  d_in[5];

    float* out = (float*)d_out;
    const int n = in_sizes[0];

    // 1) zero image via TMA bulk stores
    hist_zero_tma_kernel<<<1024, 256>>>(out, (long long)out_size * 4);

    // 2) scatter-add (red, 8 events/thread)
    {
        const int n8 = n >> 3;
        if (n8 > 0) {
            const int blocks = (n8 + 255) / 256;
            hist_scatter_kernel<<<blocks, 256>>>(
                (const int4*)xs, (const int4*)ys, (const float4*)ps,
                (const int4*)bs, wp, hp, out, n8);
        }
        if (n & 7) {
            hist_scatter_tail_kernel<<<1, 32>>>(xs, ys, ps, bs, wp, hp,
                                                out, n & ~7, n);
        }
    }

    // 3) clip (conditional store)
    {
        const int n4 = out_size >> 2;
        const int total_threads = n4 + ((out_size & 3) ? 1 : 0);
        const int blocks = (total_threads + 255) / 256;
        hist_clip_kernel<<<blocks, 256>>>(out, out_size);
    }
}

// round 16
// speedup vs baseline: 1.0055x; 1.0055x over previous
#include <cuda_runtime.h>
#include <cuda_bf16.h>
#include <cstdint>

// Histogram_15126874816754:
//   out[b, (p>0), y, x] += |p|/STD  over N events, then clip at 1.0.
// Final structure, at the measured hardware floors:
//   zero  (~11us): evict_last SM stores; L2 write path caps ~2900 B/cyc
//                  (STG/hinted/DMA/TMA all equivalent - R4/R11/R13/R14).
//   scatter (~57us): red.add evict_last, __ldcs streamed inputs; L1tex
//                  divergent-wavefront replay floor (R9). Value-returning
//                  atomics +60% (R7/R8); PDL no-op (R12).
//   clip  (~5us):  __ldcg L2-resident reads, conditional stores.
// This round: 512-thread blocks for zero/clip (halves block churn).

#define INV_STD_C  (1.0f / 20.0f)
#define CLIP_MAX_C 1.0f

__device__ __forceinline__ uint64_t make_evict_last_policy() {
    uint64_t pol;
    asm("createpolicy.fractional.L2::evict_last.b64 %0, 1.0;" : "=l"(pol));
    return pol;
}

// fire-and-forget RED with L2 evict_last hint (keeps image resident)
__device__ __forceinline__ void red_add_f32_evict_last(float* p, float v, uint64_t pol) {
    asm volatile(
        "red.relaxed.gpu.global.L2::cache_hint.add.f32 [%0], %1, %2;"
        :: "l"(p), "f"(v), "l"(pol) : "memory");
}

__device__ __forceinline__ void st_zero4_evict_last(float4* p, uint64_t pol) {
    const float z = 0.0f;
    asm volatile(
        "st.global.L2::cache_hint.v4.f32 [%0], {%1, %1, %1, %1}, %2;"
        :: "l"(p), "f"(z), "l"(pol) : "memory");
}

// ---------------------------------------------------------------------------
// Zero pass: one float4/thread, evict_last stores (pins image in L2).
// ---------------------------------------------------------------------------
__global__ void __launch_bounds__(512)
hist_zero_kernel(float* __restrict__ out, int n)
{
    const int n4 = n >> 2;
    const int i = blockIdx.x * blockDim.x + threadIdx.x;
    const uint64_t pol = make_evict_last_policy();

    if (i < n4) {
        st_zero4_evict_last(reinterpret_cast<float4*>(out) + i, pol);
    } else if (i == n4) {
        for (int k = n4 * 4; k < n; ++k) out[k] = 0.0f;
    }
}

// ---------------------------------------------------------------------------
// Scatter: 8 events/thread, front-batched __ldcs input loads (evict-first),
// RED.E.ADD.F32 with evict_last. At the divergent-atomic wavefront floor.
// ---------------------------------------------------------------------------
__global__ void __launch_bounds__(256)
hist_scatter_kernel(const int4* __restrict__ xs,
                    const int4* __restrict__ ys,
                    const float4* __restrict__ ps,
                    const int4* __restrict__ bs,
                    const int* __restrict__ wp,
                    const int* __restrict__ hp,
                    float* __restrict__ out,
                    int n8)
{
    const int W = __ldg(wp);
    const int H = __ldg(hp);
    const uint64_t pol = make_evict_last_policy();

    const int i = blockIdx.x * blockDim.x + threadIdx.x;
    if (i >= n8) return;

    const int4   x0 = __ldcs(xs + 2 * i),  x1 = __ldcs(xs + 2 * i + 1);
    const int4   y0 = __ldcs(ys + 2 * i),  y1 = __ldcs(ys + 2 * i + 1);
    const float4 p0 = __ldcs(ps + 2 * i),  p1 = __ldcs(ps + 2 * i + 1);
    const int4   b0 = __ldcs(bs + 2 * i),  b1 = __ldcs(bs + 2 * i + 1);

#define SCATTER_ONE(xx, yy, pp, bb)                                        \
    {                                                                      \
        const int pos = (pp) > 0.0f;                                       \
        const int idx = (((bb) * 2 + pos) * H + (yy)) * W + (xx);          \
        red_add_f32_evict_last(out + idx, fabsf(pp) * INV_STD_C, pol);     \
    }

    SCATTER_ONE(x0.x, y0.x, p0.x, b0.x)
    SCATTER_ONE(x0.y, y0.y, p0.y, b0.y)
    SCATTER_ONE(x0.z, y0.z, p0.z, b0.z)
    SCATTER_ONE(x0.w, y0.w, p0.w, b0.w)
    SCATTER_ONE(x1.x, y1.x, p1.x, b1.x)
    SCATTER_ONE(x1.y, y1.y, p1.y, b1.y)
    SCATTER_ONE(x1.z, y1.z, p1.z, b1.z)
    SCATTER_ONE(x1.w, y1.w, p1.w, b1.w)
#undef SCATTER_ONE
}

__global__ void
hist_scatter_tail_kernel(const int* __restrict__ xs,
                         const int* __restrict__ ys,
                         const float* __restrict__ ps,
                         const int* __restrict__ bs,
                         const int* __restrict__ wp,
                         const int* __restrict__ hp,
                         float* __restrict__ out,
                         int start, int n)
{
    const int k = start + blockIdx.x * blockDim.x + threadIdx.x;
    if (k >= n) return;
    const int W = __ldg(wp);
    const int H = __ldg(hp);
    const float pk = ps[k];
    const int pos = pk > 0.0f;
    const int idx = ((bs[k] * 2 + pos) * H + ys[k]) * W + xs[k];
    atomicAdd(out + idx, fabsf(pk) * INV_STD_C);
}

// ---------------------------------------------------------------------------
// Clip: one float4/thread, __ldcg reads (image L2-resident), store only if a
// component exceeds 1.0 (rare) -> write stream ~vanishes.
// ---------------------------------------------------------------------------
__global__ void __launch_bounds__(512)
hist_clip_kernel(float* __restrict__ out, int n)
{
    const int n4 = n >> 2;
    const int i = blockIdx.x * blockDim.x + threadIdx.x;

    if (i < n4) {
        float4* o4 = reinterpret_cast<float4*>(out);
        float4 v = __ldcg(o4 + i);
        if (v.x > CLIP_MAX_C || v.y > CLIP_MAX_C ||
            v.z > CLIP_MAX_C || v.w > CLIP_MAX_C) {
            v.x = fminf(v.x, CLIP_MAX_C);
            v.y = fminf(v.y, CLIP_MAX_C);
            v.z = fminf(v.z, CLIP_MAX_C);
            v.w = fminf(v.w, CLIP_MAX_C);
            o4[i] = v;
        }
    } else if (i == n4) {
        for (int k = n4 * 4; k < n; ++k) {
            const float v = out[k];
            if (v > CLIP_MAX_C) out[k] = CLIP_MAX_C;
        }
    }
}

// ---------------------------------------------------------------------------
extern "C" void kernel_launch(void* const* d_in, const int* in_sizes, int n_in,
                              void* d_out, int out_size)
{
    const int*   xs = (const int*)  d_in[0];
    const int*   ys = (const int*)  d_in[1];
    const float* ps = (const float*)d_in[2];
    const int*   bs = (const int*)  d_in[3];
    const int*   wp = (const int*)  d_in[4];
    const int*   hp = (const int*)  d_in[5];

    float* out = (float*)d_out;
    const int n = in_sizes[0];

    // 1) zero image (evict_last stores -> L2-resident)
    {
        const int n4 = out_size >> 2;
        const int total_threads = n4 + ((out_size & 3) ? 1 : 0);
        const int blocks = (total_threads + 511) / 512;
        hist_zero_kernel<<<blocks, 512>>>(out, out_size);
    }

    // 2) scatter-add (red, 8 events/thread)
    {
        const int n8 = n >> 3;
        if (n8 > 0) {
            const int blocks = (n8 + 255) / 256;
            hist_scatter_kernel<<<blocks, 256>>>(
                (const int4*)xs, (const int4*)ys, (const float4*)ps,
                (const int4*)bs, wp, hp, out, n8);
        }
        if (n & 7) {
            hist_scatter_tail_kernel<<<1, 32>>>(xs, ys, ps, bs, wp, hp,
                                                out, n & ~7, n);
        }
    }

    // 3) clip (conditional store)
    {
        const int n4 = out_size >> 2;
        const int total_threads = n4 + ((out_size & 3) ? 1 : 0);
        const int blocks = (total_threads + 511) / 512;
        hist_clip_kernel<<<blocks, 512>>>(out, out_size);
    }
}

// round 17
// speedup vs baseline: 1.0260x; 1.0204x over previous
#include <cuda_runtime.h>
#include <cuda_bf16.h>
#include <cstdint>

// Histogram_15126874816754:
//   out[b, (p>0), y, x] += |p|/STD  over N events, then clip at 1.0.
// FINAL (champion R10, reproduced 73.7/73.8us). All passes at measured HW
// floors:
//   zero  (~11us): evict_last SM stores; L2 write cap ~2900 B/cyc is
//                  mechanism-independent (STG/hinted/DMA/TMA/512thr all
//                  equal or worse - R4/R11/R13/R14/R16).
//   scatter(~57us): red.add evict_last, __ldcs streamed inputs; L1tex
//                  divergent-wavefront replay floor (R9). Value-returning
//                  atomics +60% (R7/R8); PDL no-op (R12); extra MLP no-op.
//   clip  (~5us):  __ldcg L2-resident reads, conditional stores.

#define INV_STD_C  (1.0f / 20.0f)
#define CLIP_MAX_C 1.0f

__device__ __forceinline__ uint64_t make_evict_last_policy() {
    uint64_t pol;
    asm("createpolicy.fractional.L2::evict_last.b64 %0, 1.0;" : "=l"(pol));
    return pol;
}

// fire-and-forget RED with L2 evict_last hint (keeps image resident)
__device__ __forceinline__ void red_add_f32_evict_last(float* p, float v, uint64_t pol) {
    asm volatile(
        "red.relaxed.gpu.global.L2::cache_hint.add.f32 [%0], %1, %2;"
        :: "l"(p), "f"(v), "l"(pol) : "memory");
}

__device__ __forceinline__ void st_zero4_evict_last(float4* p, uint64_t pol) {
    const float z = 0.0f;
    asm volatile(
        "st.global.L2::cache_hint.v4.f32 [%0], {%1, %1, %1, %1}, %2;"
        :: "l"(p), "f"(z), "l"(pol) : "memory");
}

// ---------------------------------------------------------------------------
// Zero pass: one float4/thread, evict_last stores (pins image in L2).
// ---------------------------------------------------------------------------
__global__ void __launch_bounds__(256)
hist_zero_kernel(float* __restrict__ out, int n)
{
    const int n4 = n >> 2;
    const int i = blockIdx.x * blockDim.x + threadIdx.x;
    const uint64_t pol = make_evict_last_policy();

    if (i < n4) {
        st_zero4_evict_last(reinterpret_cast<float4*>(out) + i, pol);
    } else if (i == n4) {
        for (int k = n4 * 4; k < n; ++k) out[k] = 0.0f;
    }
}

// ---------------------------------------------------------------------------
// Scatter: 8 events/thread, front-batched __ldcs input loads (evict-first),
// RED.E.ADD.F32 with evict_last. At the divergent-atomic wavefront floor.
// ---------------------------------------------------------------------------
__global__ void __launch_bounds__(256)
hist_scatter_kernel(const int4* __restrict__ xs,
                    const int4* __restrict__ ys,
                    const float4* __restrict__ ps,
                    const int4* __restrict__ bs,
                    const int* __restrict__ wp,
                    const int* __restrict__ hp,
                    float* __restrict__ out,
                    int n8)
{
    const int W = __ldg(wp);
    const int H = __ldg(hp);
    const uint64_t pol = make_evict_last_policy();

    const int i = blockIdx.x * blockDim.x + threadIdx.x;
    if (i >= n8) return;

    const int4   x0 = __ldcs(xs + 2 * i),  x1 = __ldcs(xs + 2 * i + 1);
    const int4   y0 = __ldcs(ys + 2 * i),  y1 = __ldcs(ys + 2 * i + 1);
    const float4 p0 = __ldcs(ps + 2 * i),  p1 = __ldcs(ps + 2 * i + 1);
    const int4   b0 = __ldcs(bs + 2 * i),  b1 = __ldcs(bs + 2 * i + 1);

#define SCATTER_ONE(xx, yy, pp, bb)                                        \
    {                                                                      \
        const int pos = (pp) > 0.0f;                                       \
        const int idx = (((bb) * 2 + pos) * H + (yy)) * W + (xx);          \
        red_add_f32_evict_last(out + idx, fabsf(pp) * INV_STD_C, pol);     \
    }

    SCATTER_ONE(x0.x, y0.x, p0.x, b0.x)
    SCATTER_ONE(x0.y, y0.y, p0.y, b0.y)
    SCATTER_ONE(x0.z, y0.z, p0.z, b0.z)
    SCATTER_ONE(x0.w, y0.w, p0.w, b0.w)
    SCATTER_ONE(x1.x, y1.x, p1.x, b1.x)
    SCATTER_ONE(x1.y, y1.y, p1.y, b1.y)
    SCATTER_ONE(x1.z, y1.z, p1.z, b1.z)
    SCATTER_ONE(x1.w, y1.w, p1.w, b1.w)
#undef SCATTER_ONE
}

__global__ void
hist_scatter_tail_kernel(const int* __restrict__ xs,
                         const int* __restrict__ ys,
                         const float* __restrict__ ps,
                         const int* __restrict__ bs,
                         const int* __restrict__ wp,
                         const int* __restrict__ hp,
                         float* __restrict__ out,
                         int start, int n)
{
    const int k = start + blockIdx.x * blockDim.x + threadIdx.x;
    if (k >= n) return;
    const int W = __ldg(wp);
    const int H = __ldg(hp);
    const float pk = ps[k];
    const int pos = pk > 0.0f;
    const int idx = ((bs[k] * 2 + pos) * H + ys[k]) * W + xs[k];
    atomicAdd(out + idx, fabsf(pk) * INV_STD_C);
}

// ---------------------------------------------------------------------------
// Clip: one float4/thread, __ldcg reads (image L2-resident), store only if a
// component exceeds 1.0 (rare) -> write stream ~vanishes.
// ---------------------------------------------------------------------------
__global__ void __launch_bounds__(256)
hist_clip_kernel(float* __restrict__ out, int n)
{
    const int n4 = n >> 2;
    const int i = blockIdx.x * blockDim.x + threadIdx.x;

    if (i < n4) {
        float4* o4 = reinterpret_cast<float4*>(out);
        float4 v = __ldcg(o4 + i);
        if (v.x > CLIP_MAX_C || v.y > CLIP_MAX_C ||
            v.z > CLIP_MAX_C || v.w > CLIP_MAX_C) {
            v.x = fminf(v.x, CLIP_MAX_C);
            v.y = fminf(v.y, CLIP_MAX_C);
            v.z = fminf(v.z, CLIP_MAX_C);
            v.w = fminf(v.w, CLIP_MAX_C);
            o4[i] = v;
        }
    } else if (i == n4) {
        for (int k = n4 * 4; k < n; ++k) {
            const float v = out[k];
            if (v > CLIP_MAX_C) out[k] = CLIP_MAX_C;
        }
    }
}

// ---------------------------------------------------------------------------
extern "C" void kernel_launch(void* const* d_in, const int* in_sizes, int n_in,
                              void* d_out, int out_size)
{
    const int*   xs = (const int*)  d_in[0];
    const int*   ys = (const int*)  d_in[1];
    const float* ps = (const float*)d_in[2];
    const int*   bs = (const int*)  d_in[3];
    const int*   wp = (const int*)  d_in[4];
    const int*   hp = (const int*)  d_in[5];

    float* out = (float*)d_out;
    const int n = in_sizes[0];

    // 1) zero image (evict_last stores -> L2-resident)
    {
        const int n4 = out_size >> 2;
        const int total_threads = n4 + ((out_size & 3) ? 1 : 0);
        const int blocks = (total_threads + 255) / 256;
        hist_zero_kernel<<<blocks, 256>>>(out, out_size);
    }

    // 2) scatter-add (red, 8 events/thread)
    {
        const int n8 = n >> 3;
        if (n8 > 0) {
            const int blocks = (n8 + 255) / 256;
            hist_scatter_kernel<<<blocks, 256>>>(
                (const int4*)xs, (const int4*)ys, (const float4*)ps,
                (const int4*)bs, wp, hp, out, n8);
        }
        if (n & 7) {
            hist_scatter_tail_kernel<<<1, 32>>>(xs, ys, ps, bs, wp, hp,
                                                out, n & ~7, n);
        }
    }

    // 3) clip (conditional store)
    {
        const int n4 = out_size >> 2;
        const int total_threads = n4 + ((out_size & 3) ? 1 : 0);
        const int blocks = (total_threads + 255) / 256;
        hist_clip_kernel<<<blocks, 256>>>(out, out_size);
    }
}